// round 4
// baseline (speedup 1.0000x reference)
#include <cuda_runtime.h>
#include <stdint.h>

#define NB 32
#define CI 32
#define CO 32
#define HH 128
#define WW 128

// Scratch (static __device__ arrays: allocation-free, graph-safe)
__device__ signed char g_act_nhwc[(size_t)NB * HH * WW * CI];  // 16 MB, NHWC int8
__device__ int g_acc[(size_t)NB * CO * HH * WW];               // 64 MB, NCHW int32
__device__ int g_max;
__device__ unsigned g_wpack[CO * 9 * (CI / 4)];                // dp4a-packed weights

__global__ void k_init() { g_max = 0; }

// weight (Co,Ci,3,3) int32 -> g_wpack[(co*9 + tap)*8 + ci/4], 4 ci bytes/word
__global__ void k_packw(const int* __restrict__ w) {
    int i = blockIdx.x * blockDim.x + threadIdx.x;
    if (i >= CO * 9 * 8) return;
    int ci4 = i & 7;
    int t = (i >> 3) % 9;
    int co = i / 72;
    int kh = t / 3, kw = t - kh * 3;
    unsigned v = 0;
#pragma unroll
    for (int j = 0; j < 4; j++) {
        int ci = ci4 * 4 + j;
        unsigned b = (unsigned)(w[((co * CI + ci) * 3 + kh) * 3 + kw]) & 0xFFu;
        v |= b << (8 * j);
    }
    g_wpack[i] = v;
}

// NCHW int32 -> NHWC int8 (channels contiguous for dp4a)
__global__ void k_transpose(const int* __restrict__ act) {
    int p = blockIdx.x * blockDim.x + threadIdx.x;  // over NB*HH*WW pixels
    int x = p & (WW - 1);
    int y = (p >> 7) & (HH - 1);
    int n = p >> 14;
    unsigned* dst = (unsigned*)(g_act_nhwc + (size_t)p * CI);
#pragma unroll
    for (int j = 0; j < 8; j++) {
        unsigned v = 0;
#pragma unroll
        for (int b = 0; b < 4; b++) {
            int ci = j * 4 + b;
            unsigned c = (unsigned)(act[((size_t)(n * CI + ci) * HH + y) * WW + x]) & 0xFFu;
            v |= c << (8 * b);
        }
        dst[j] = v;
    }
}

// Direct conv: 1 thread = 1 output pixel, all 32 Co accumulators.
// Weights broadcast from smem; acc -> g_acc; |acc| max -> atomicMax.
__global__ void k_conv() {
    __shared__ uint4 sw[CO * 9 * 2];
    int tid = threadIdx.x;
    const uint4* wp = (const uint4*)g_wpack;
    for (int i = tid; i < CO * 9 * 2; i += blockDim.x) sw[i] = wp[i];
    __syncthreads();

    int b = blockIdx.x;               // NB*64 blocks, 256 threads: 2 rows/block
    int n = b >> 6;
    int y = ((b & 63) << 1) | (tid >> 7);
    int x = tid & 127;

    int acc[CO];
#pragma unroll
    for (int co = 0; co < CO; co++) acc[co] = 0;

#pragma unroll 1
    for (int t = 0; t < 9; t++) {
        int ky = t / 3, kx = t - ky * 3;
        int iy = y + ky - 1, ix = x + kx - 1;
        uint4 a0 = make_uint4(0, 0, 0, 0), a1 = make_uint4(0, 0, 0, 0);
        if ((unsigned)iy < HH && (unsigned)ix < WW) {
            const uint4* ap =
                (const uint4*)(g_act_nhwc + ((((size_t)n * HH + iy) * WW + ix) << 5));
            a0 = ap[0];
            a1 = ap[1];
        }
#pragma unroll
        for (int co = 0; co < CO; co++) {
            uint4 w0 = sw[(co * 9 + t) * 2];
            uint4 w1 = sw[(co * 9 + t) * 2 + 1];
            int s = acc[co];
            s = __dp4a((int)a0.x, (int)w0.x, s);
            s = __dp4a((int)a0.y, (int)w0.y, s);
            s = __dp4a((int)a0.z, (int)w0.z, s);
            s = __dp4a((int)a0.w, (int)w0.w, s);
            s = __dp4a((int)a1.x, (int)w1.x, s);
            s = __dp4a((int)a1.y, (int)w1.y, s);
            s = __dp4a((int)a1.z, (int)w1.z, s);
            s = __dp4a((int)a1.w, (int)w1.w, s);
            acc[co] = s;
        }
    }

    int m = 0;
    size_t base = ((size_t)n * CO * HH + y) * WW + x;
#pragma unroll
    for (int co = 0; co < CO; co++) {
        g_acc[base + (size_t)co * HH * WW] = acc[co];
        int a = acc[co];
        m = max(m, a < 0 ? -a : a);
    }
    m = __reduce_max_sync(0xffffffffu, m);
    if ((tid & 31) == 0) atomicMax(&g_max, m);
}

// Bit-exact replica of psto_shift + act_calc select paths.
__device__ __forceinline__ int quantize_one(int v, int shift, int eff) {
    if (shift < 1) return (int)(signed char)v;  // truncating int8 cast (astype)
    int rt = v >> eff;                          // floor division by 2^eff
    int prob = v - (rt << eff);                 // remainder in [0, 2^eff)
    int h = eff >> 1;
    int qp = prob >> h;
    int pr = prob & ((1 << h) - 1);
    if (eff & 1) pr <<= 1;
    int sgn = (v > 0) - (v < 0);
    int r = rt + ((qp <= pr) ? 0 : sgn);
    r = r < -127 ? -127 : (r > 127 ? 127 : r);
    return r;
}

__global__ void k_quant(const int* __restrict__ expin,
                        const int* __restrict__ wexp,
                        float* __restrict__ out, int out_size) {
    int gmax = g_max;
    // exact integer ceil(log2(r)), r>0: 32 - clz(r-1); r==0 -> 0
    int bw = gmax ? (32 - __clz(gmax - 1)) : 0;
    int shift = bw - 7;
    int eff = shift > 1 ? shift : 2;

    int idx = blockIdx.x * blockDim.x + threadIdx.x;
    int nelem4 = (out_size - 1) >> 2;
    if (idx < nelem4) {
        int4 a = ((const int4*)g_acc)[idx];
        float4 r;
        r.x = (float)quantize_one(a.x, shift, eff);
        r.y = (float)quantize_one(a.y, shift, eff);
        r.z = (float)quantize_one(a.z, shift, eff);
        r.w = (float)quantize_one(a.w, shift, eff);
        ((float4*)out)[idx] = r;
    }
    if (idx == 0) {
        int inc = shift > 1 ? shift : (shift == 1 ? 2 : 0);
        // reference: int32 add, then astype(int8) (wraparound)
        int e = expin[0] + wexp[0] + inc;
        out[out_size - 1] = (float)(signed char)e;
    }
}

extern "C" void kernel_launch(void* const* d_in, const int* in_sizes, int n_in,
                              void* d_out, int out_size) {
    const int* act = (const int*)d_in[0];
    const int* expin = (const int*)d_in[1];
    const int* w = (const int*)d_in[2];
    const int* wexp = (const int*)d_in[3];
    float* out = (float*)d_out;

    k_init<<<1, 1>>>();
    k_packw<<<(CO * 9 * 8 + 255) / 256, 256>>>(w);
    k_transpose<<<(NB * HH * WW) / 256, 256>>>(act);
    k_conv<<<NB * 64, 256>>>();
    int nelem4 = (out_size - 1) / 4;
    k_quant<<<(nelem4 + 255) / 256, 256>>>(expin, wexp, out, out_size);
}

// round 5
// speedup vs baseline: 1.5979x; 1.5979x over previous
#include <cuda_runtime.h>
#include <stdint.h>

#define NB 32
#define CI 32
#define CO 32
#define HH 128
#define WW 128

// Scratch (static __device__ arrays: allocation-free, graph-safe)
__device__ signed char g_act_nhwc[(size_t)NB * HH * WW * CI];  // 16 MB NHWC int8
__device__ int g_acc[(size_t)NB * CO * HH * WW];               // 64 MB NCHW int32
__device__ int g_max;
__device__ unsigned g_wpack[CO * 9 * 8];                       // packed weights

// pack weights (Co,Ci,3,3) int32 -> g_wpack[(co*9+tap)*8 + ci/4]; also init g_max
__global__ void k_packw(const int* __restrict__ w) {
    int i = blockIdx.x * blockDim.x + threadIdx.x;
    if (i == 0) g_max = 0;
    if (i >= CO * 9 * 8) return;
    int ciw = i & 7;
    int t = (i >> 3) % 9;
    int co = i / 72;
    int kh = t / 3, kw = t - kh * 3;
    unsigned v = 0;
#pragma unroll
    for (int j = 0; j < 4; j++) {
        int ci = ciw * 4 + j;
        unsigned b = (unsigned)(w[((co * CI + ci) * 3 + kh) * 3 + kw]) & 0xFFu;
        v |= b << (8 * j);
    }
    g_wpack[i] = v;
}

// NCHW int32 -> NHWC int8 (4 ci per word, ci0 in low byte)
__global__ void k_transpose(const int* __restrict__ act) {
    int p = blockIdx.x * blockDim.x + threadIdx.x;
    int x = p & (WW - 1);
    int y = (p >> 7) & (HH - 1);
    int n = p >> 14;
    unsigned* dst = (unsigned*)(g_act_nhwc + (size_t)p * CI);
#pragma unroll
    for (int j = 0; j < 8; j++) {
        unsigned v = 0;
#pragma unroll
        for (int b = 0; b < 4; b++) {
            int ci = j * 4 + b;
            unsigned c = (unsigned)(act[((size_t)(n * CI + ci) * HH + y) * WW + x]) & 0xFFu;
            v |= c << (8 * b);
        }
        dst[j] = v;
    }
}

__device__ __forceinline__ void mma_s8(int d[4], unsigned a0, unsigned a1,
                                       unsigned a2, unsigned a3,
                                       unsigned b0, unsigned b1) {
    asm volatile(
        "mma.sync.aligned.m16n8k32.row.col.s32.s8.s8.s32 "
        "{%0,%1,%2,%3}, {%4,%5,%6,%7}, {%8,%9}, {%0,%1,%2,%3};\n"
        : "+r"(d[0]), "+r"(d[1]), "+r"(d[2]), "+r"(d[3])
        : "r"(a0), "r"(a1), "r"(a2), "r"(a3), "r"(b0), "r"(b1));
}

// Implicit-GEMM conv via warp IMMA. Block = 2 output rows (n fixed).
// 8 warps: warp w -> row (w>>2), x-segment (w&3)*32. Warp tile = 32 px x 32 co.
__global__ void __launch_bounds__(256) k_conv() {
    __shared__ signed char s_act[4 * 130 * 32];  // rows y0-1..y0+2, x halo, 16640 B
    __shared__ unsigned s_w[9 * 32 * 8];         // [tap][co][ciw], 9216 B

    int tid = threadIdx.x;
    int b = blockIdx.x;
    int n = b >> 6;
    int y0 = (b & 63) << 1;

    // zero act tile (covers halo rows/cols)
    uint4* sa4 = (uint4*)s_act;
#pragma unroll
    for (int i = tid; i < 4 * 130 * 32 / 16; i += 256) sa4[i] = make_uint4(0, 0, 0, 0);
    // weights: reorder (co,t,ciw) -> (t,co,ciw)
    for (int i = tid; i < 9 * 32 * 8; i += 256) {
        int ciw = i & 7;
        int co = (i >> 3) & 31;
        int t = i >> 8;
        s_w[i] = g_wpack[(co * 9 + t) * 8 + ciw];
    }
    __syncthreads();

    // fill interior: 4 rows x 128 px x 32B; one uint4 (half pixel) per thread per row
    {
        int px = tid >> 1;
        int half = (tid & 1) << 4;
#pragma unroll
        for (int r = 0; r < 4; r++) {
            int iy = y0 + r - 1;
            if ((unsigned)iy < HH) {
                const uint4* src = (const uint4*)(g_act_nhwc +
                    ((((size_t)n * HH + iy) * WW + px) << 5) + half);
                *(uint4*)(s_act + ((r * 130 + px + 1) * 32) + half) = *src;
            }
        }
    }
    __syncthreads();

    int lane = tid & 31;
    int wid = tid >> 5;
    int g = lane >> 2;
    int tig = lane & 3;
    int row = wid >> 2;
    int xbase = (wid & 3) << 5;

    int acc[2][4][4];
#pragma unroll
    for (int m = 0; m < 2; m++)
#pragma unroll
        for (int ns = 0; ns < 4; ns++)
#pragma unroll
            for (int k = 0; k < 4; k++) acc[m][ns][k] = 0;

#pragma unroll 1
    for (int t = 0; t < 9; t++) {
        int ky = t / 3, kx = t - 3 * (t / 3);
        const signed char* arow = s_act + ((row + ky) * 130 + xbase + kx) * 32;
        unsigned a0[2], a1[2], a2[2], a3[2];
#pragma unroll
        for (int m = 0; m < 2; m++) {
            const unsigned* p0 = (const unsigned*)(arow + (m * 16 + g) * 32) + tig;
            const unsigned* p1 = (const unsigned*)(arow + (m * 16 + g + 8) * 32) + tig;
            a0[m] = p0[0];
            a2[m] = p0[4];  // ci +16
            a1[m] = p1[0];
            a3[m] = p1[4];
        }
#pragma unroll
        for (int ns = 0; ns < 4; ns++) {
            const unsigned* pw = &s_w[(t * 32 + ns * 8 + g) * 8 + tig];
            unsigned b0 = pw[0], b1 = pw[4];
#pragma unroll
            for (int m = 0; m < 2; m++)
                mma_s8(acc[m][ns], a0[m], a1[m], a2[m], a3[m], b0, b1);
        }
    }

    // store NCHW acc + fused |max| reduction
    int y = y0 + row;
    int mloc = 0;
#pragma unroll
    for (int m = 0; m < 2; m++)
#pragma unroll
        for (int ns = 0; ns < 4; ns++) {
            int x0p = xbase + m * 16 + g;
            int co0 = ns * 8 + tig * 2;
            int* base0 = g_acc + (((n * 32 + co0) * 128 + y) * 128);
            int* base1 = base0 + 128 * 128;  // co0+1
            base0[x0p] = acc[m][ns][0];
            base1[x0p] = acc[m][ns][1];
            base0[x0p + 8] = acc[m][ns][2];
            base1[x0p + 8] = acc[m][ns][3];
#pragma unroll
            for (int k = 0; k < 4; k++) {
                int a = acc[m][ns][k];
                mloc = max(mloc, a < 0 ? -a : a);
            }
        }
    mloc = __reduce_max_sync(0xffffffffu, mloc);
    if (lane == 0) atomicMax(&g_max, mloc);
}

// Bit-exact replica of psto_shift + act_calc select paths.
__device__ __forceinline__ int quantize_one(int v, int shift, int eff) {
    if (shift < 1) return (int)(signed char)v;  // truncating int8 cast (astype)
    int rt = v >> eff;                          // floor division by 2^eff
    int prob = v - (rt << eff);                 // remainder in [0, 2^eff)
    int h = eff >> 1;
    int qp = prob >> h;
    int pr = prob & ((1 << h) - 1);
    if (eff & 1) pr <<= 1;
    int sgn = (v > 0) - (v < 0);
    int r = rt + ((qp <= pr) ? 0 : sgn);
    r = r < -127 ? -127 : (r > 127 ? 127 : r);
    return r;
}

__global__ void k_quant(const int* __restrict__ expin,
                        const int* __restrict__ wexp,
                        float* __restrict__ out, int out_size) {
    int gmax = g_max;
    int bw = gmax ? (32 - __clz(gmax - 1)) : 0;  // exact ceil(log2)
    int shift = bw - 7;
    int eff = shift > 1 ? shift : 2;

    int idx = blockIdx.x * blockDim.x + threadIdx.x;
    int nelem4 = (out_size - 1) >> 2;
    if (idx < nelem4) {
        int4 a = ((const int4*)g_acc)[idx];
        float4 r;
        r.x = (float)quantize_one(a.x, shift, eff);
        r.y = (float)quantize_one(a.y, shift, eff);
        r.z = (float)quantize_one(a.z, shift, eff);
        r.w = (float)quantize_one(a.w, shift, eff);
        ((float4*)out)[idx] = r;
    }
    if (idx == 0) {
        int inc = shift > 1 ? shift : (shift == 1 ? 2 : 0);
        int e = expin[0] + wexp[0] + inc;
        out[out_size - 1] = (float)(signed char)e;
    }
}

extern "C" void kernel_launch(void* const* d_in, const int* in_sizes, int n_in,
                              void* d_out, int out_size) {
    const int* act = (const int*)d_in[0];
    const int* expin = (const int*)d_in[1];
    const int* w = (const int*)d_in[2];
    const int* wexp = (const int*)d_in[3];
    float* out = (float*)d_out;

    k_packw<<<(CO * 9 * 8 + 255) / 256, 256>>>(w);
    k_transpose<<<(NB * HH * WW) / 256, 256>>>(act);
    k_conv<<<NB * 64, 256>>>();
    int nelem4 = (out_size - 1) / 4;
    k_quant<<<(nelem4 + 255) / 256, 256>>>(expin, wexp, out, out_size);
}